// round 1
// baseline (speedup 1.0000x reference)
#include <cuda_runtime.h>

// ---------------- constants ----------------
#define OFF_IDX   1572864
#define OFF_LOSS  1574912
#define OFF_ZE    1574913
#define OUT_FULL  1705985

// ---------------- scratch (device globals; no allocation) ----------------
__device__ float g_h1[32 * 128 * 64 * 64];   // conv1 output (relu'd)
__device__ float g_hp[32 * 128 * 64];        // pooled encoder features [n][c][bi*8+bj]
__device__ float g_ze[2048 * 64];            // z_e as [p][d]
__device__ int   g_idx[2048];
__device__ float g_loss;
__device__ float g_r[2048 * 128];            // relu(dproj(z_q)) as [p][c]
__device__ float g_q[9 * 2048 * 128];        // per-tap block contractions [t][g][o]
__device__ float g_xblk[27 * 2048];          // 9 pixel-types x 3 ch per block
__device__ float g_w2t[128 * 9 * 128];       // enc_w2 transposed: [ic][tap][oc]
__device__ float g_wt1[9 * 128 * 128];       // dconv1_w transposed: [tap][c][o]

// ---------------- prep: weight transposes + loss zero ----------------
__global__ void k_prep(const float* __restrict__ w2, const float* __restrict__ w1d) {
    int id = blockIdx.x * 256 + threadIdx.x;
    if (id == 0) g_loss = 0.f;
    if (id < 128 * 9 * 128) {
        {   // g_w2t[(ic*9+tap)*128+oc] = w2[(oc*128+ic)*9+tap]
            int ic = id / 1152, rem = id % 1152, tap = rem / 128, oc = rem % 128;
            g_w2t[id] = w2[(oc * 128 + ic) * 9 + tap];
        }
        {   // g_wt1[(t*128+c)*128+o] = w1d[(o*128+c)*9+t]
            int t = id / 16384, rem = id % 16384, c = rem / 128, o = rem % 128;
            g_wt1[id] = w1d[(o * 128 + c) * 9 + t];
        }
    }
}

// ---------------- conv1: 3->128, 3x3, stride2, pad1, relu ----------------
__global__ void k_conv1(const float* __restrict__ x, const float* __restrict__ w,
                        const float* __restrict__ b) {
    __shared__ float sw[128 * 27];
    __shared__ float sb[128];
    int n = blockIdx.z, yt = blockIdx.y, xt = blockIdx.x;
    int tid = threadIdx.x;
    for (int i = tid; i < 128 * 27; i += 256) sw[i] = w[i];
    if (tid < 128) sb[tid] = b[tid];
    int ox = xt * 16 + (tid & 15);
    int oy = yt * 16 + (tid >> 4);
    float iv[27];
    const float* xb = x + n * 3 * 16384;
#pragma unroll
    for (int c = 0; c < 3; c++)
#pragma unroll
        for (int di = 0; di < 3; di++) {
            int gy = 2 * oy + di - 1;
#pragma unroll
            for (int dj = 0; dj < 3; dj++) {
                int gx = 2 * ox + dj - 1;
                float v = 0.f;
                if (gy >= 0 && gy < 128 && gx >= 0 && gx < 128)
                    v = xb[(c * 128 + gy) * 128 + gx];
                iv[c * 9 + di * 3 + dj] = v;
            }
        }
    __syncthreads();
    float* ob = g_h1 + n * 128 * 4096 + oy * 64 + ox;
#pragma unroll 4
    for (int o = 0; o < 128; o++) {
        float acc = sb[o];
#pragma unroll
        for (int k = 0; k < 27; k++) acc = fmaf(sw[o * 27 + k], iv[k], acc);
        ob[o * 4096] = fmaxf(acc, 0.f);
    }
}

// ---------------- conv2: 128->128, 3x3, stride2, pad1, relu, fused 4x4 avgpool ----------------
// block: (rowg 0..7, ocg 0..1, n 0..31); 256 threads; thread = (grp 0..7, xo 0..31)
// computes 8 oc x 4 out-rows x 1 col; pools rows in-thread, cols via shfl.
__global__ void k_conv2pool(const float* __restrict__ b2) {
    extern __shared__ float sm[];
    float* sIn = sm;                 // 16 ic x 9 rows x 66 cols
    float* sW  = sm + 16 * 9 * 66;   // 16 ic x 9 taps x 64 oc
    int rowg = blockIdx.x, ocg = blockIdx.y, n = blockIdx.z;
    int tid = threadIdx.x;
    int xo = tid & 31, grp = tid >> 5;
    float acc[8][4];
#pragma unroll
    for (int k = 0; k < 8; k++)
#pragma unroll
        for (int r = 0; r < 4; r++) acc[k][r] = 0.f;

    for (int chunk = 0; chunk < 8; chunk++) {
        int ic0 = chunk * 16;
        __syncthreads();
        for (int i = tid; i < 16 * 9 * 64; i += 256) {
            int c = i / 576; int rem = i - c * 576; int tap = rem >> 6; int k = rem & 63;
            sW[i] = g_w2t[((ic0 + c) * 9 + tap) * 128 + ocg * 64 + k];
        }
        for (int i = tid; i < 16 * 9 * 65; i += 256) {
            int c = i / 585; int rem = i - c * 585; int ri = rem / 65; int col = rem - ri * 65;
            int gy = rowg * 8 + ri - 1;
            int gx = col - 1;
            float v = 0.f;
            if (gy >= 0 && gy < 64 && gx >= 0 && gx < 64)
                v = g_h1[((n * 128 + ic0 + c) * 64 + gy) * 64 + gx];
            sIn[(c * 9 + ri) * 66 + col] = v;
        }
        __syncthreads();
#pragma unroll 1
        for (int c = 0; c < 16; c++) {
#pragma unroll
            for (int di = 0; di < 3; di++) {
#pragma unroll
                for (int dj = 0; dj < 3; dj++) {
                    const float* wp = &sW[(c * 9 + di * 3 + dj) * 64 + grp * 8];
                    float4 wq0 = *(const float4*)wp;
                    float4 wq1 = *(const float4*)(wp + 4);
                    float wv[8] = {wq0.x, wq0.y, wq0.z, wq0.w, wq1.x, wq1.y, wq1.z, wq1.w};
                    float inv[4];
#pragma unroll
                    for (int r = 0; r < 4; r++)
                        inv[r] = sIn[(c * 9 + 2 * r + di) * 66 + 2 * xo + dj];
#pragma unroll
                    for (int k = 0; k < 8; k++)
#pragma unroll
                        for (int r = 0; r < 4; r++)
                            acc[k][r] = fmaf(wv[k], inv[r], acc[k][r]);
                }
            }
        }
    }
    // bias + relu + pool (rows in-thread; 4 cols via shfl_xor; lane == xo)
#pragma unroll
    for (int k = 0; k < 8; k++) {
        int oc = ocg * 64 + grp * 8 + k;
        float bv = b2[oc];
        float s = 0.f;
#pragma unroll
        for (int r = 0; r < 4; r++) s += fmaxf(acc[k][r] + bv, 0.f);
        s += __shfl_xor_sync(0xffffffffu, s, 1);
        s += __shfl_xor_sync(0xffffffffu, s, 2);
        if ((xo & 3) == 0)
            g_hp[(n * 128 + oc) * 64 + rowg * 8 + (xo >> 2)] = s * (1.f / 16.f);
    }
}

// ---------------- proj 1x1: 128 -> 64 (z_e) ----------------
__global__ void k_proj(const float* __restrict__ pw, const float* __restrict__ pb,
                       float* __restrict__ dout, int write_out) {
    __shared__ float spw[64 * 129];
    __shared__ float shp[8][128];
    int blk = blockIdx.x;    // 8 positions per block
    int tid = threadIdx.x;   // 256
    for (int i = tid; i < 64 * 128; i += 256) {
        int d = i >> 7, c = i & 127;
        spw[d * 129 + c] = pw[i];
    }
    for (int i = tid; i < 8 * 128; i += 256) {
        int pl = i >> 7, c = i & 127;
        int p = blk * 8 + pl;
        shp[pl][c] = g_hp[((p >> 6) * 128 + c) * 64 + (p & 63)];
    }
    __syncthreads();
    int d = tid & 63;
    int pl0 = tid >> 6;
    for (int pl = pl0; pl < 8; pl += 4) {
        int p = blk * 8 + pl;
        float acc = pb[d];
#pragma unroll 4
        for (int c = 0; c < 128; c++) acc = fmaf(spw[d * 129 + c], shp[pl][c], acc);
        g_ze[p * 64 + d] = acc;
        if (write_out) {
            int n = p >> 6, pos = p & 63;
            dout[OFF_ZE + (n * 64 + d) * 64 + pos] = acc;
        }
    }
}

// ---------------- vector quantizer: argmin + loss accumulation ----------------
__global__ void k_vq(const float* __restrict__ cb) {
    extern __shared__ float sm[];
    float* scb = sm;              // 512 x 65 (padded)
    float* sze = sm + 512 * 65;   // 8 x 64
    int tid = threadIdx.x;
    for (int i = tid; i < 512 * 64; i += 256) {
        int c = i >> 6, d = i & 63;
        scb[c * 65 + d] = cb[i];
    }
    for (int i = tid; i < 8 * 64; i += 256)
        sze[i] = g_ze[blockIdx.x * 8 * 64 + i];
    __syncthreads();
    int warp = tid >> 5, lane = tid & 31;
    int p = blockIdx.x * 8 + warp;
    const float* zp = sze + warp * 64;
    float best = 3.4e38f; int bidx = 0;
    for (int ci = 0; ci < 16; ci++) {
        int c = ci * 32 + lane;
        const float* cr = scb + c * 65;
        float dd = 0.f;
#pragma unroll 8
        for (int d = 0; d < 64; d++) {
            float t = zp[d] - cr[d];
            dd = fmaf(t, t, dd);
        }
        if (dd < best) { best = dd; bidx = c; }
    }
#pragma unroll
    for (int off = 16; off > 0; off >>= 1) {
        float ob = __shfl_down_sync(0xffffffffu, best, off);
        int   oi = __shfl_down_sync(0xffffffffu, bidx, off);
        if (ob < best || (ob == best && oi < bidx)) { best = ob; bidx = oi; }
    }
    if (lane == 0) {
        g_idx[p] = bidx;
        atomicAdd(&g_loss, best);  // best == sum_d (z-c)^2 for chosen code
    }
}

// ---------------- decoder 1x1 dproj + relu: r[p][c] ----------------
__global__ void k_dec_r(const float* __restrict__ cb, const float* __restrict__ dpw,
                        const float* __restrict__ dpb) {
    __shared__ float sdw[128 * 65];
    __shared__ float scr[8][64];
    int tid = threadIdx.x;  // 128
    for (int i = tid; i < 128 * 64; i += 128) {
        int c = i >> 6, d = i & 63;
        sdw[c * 65 + d] = dpw[i];
    }
    for (int i = tid; i < 8 * 64; i += 128) {
        int pl = i >> 6, d = i & 63;
        int p = blockIdx.x * 8 + pl;
        scr[pl][d] = cb[g_idx[p] * 64 + d];
    }
    __syncthreads();
    int c = tid;
    float bv = dpb[c];
    for (int pl = 0; pl < 8; pl++) {
        float acc = bv;
#pragma unroll 4
        for (int d = 0; d < 64; d++) acc = fmaf(sdw[c * 65 + d], scr[pl][d], acc);
        g_r[(blockIdx.x * 8 + pl) * 128 + c] = fmaxf(acc, 0.f);
    }
}

// ---------------- per-tap block contractions q[t][g][o] ----------------
__global__ void k_q() {
    __shared__ float sr[16 * 128];
    int t = blockIdx.y;
    int gt = blockIdx.x;    // 16 g per block
    int tid = threadIdx.x;  // 256
    for (int i = tid; i < 16 * 128; i += 256)
        sr[i] = g_r[gt * 16 * 128 + i];
    __syncthreads();
    int o = tid & 127, gs = tid >> 7;
    float acc[8];
#pragma unroll
    for (int j = 0; j < 8; j++) acc[j] = 0.f;
    const float* wp = g_wt1 + t * 16384 + o;
    const float* rp = sr + gs * 8 * 128;
#pragma unroll 4
    for (int c = 0; c < 128; c++) {
        float wv = wp[c * 128];
#pragma unroll
        for (int j = 0; j < 8; j++) acc[j] = fmaf(wv, rp[j * 128 + c], acc[j]);
    }
#pragma unroll
    for (int j = 0; j < 8; j++)
        g_q[(t * 2048 + gt * 16 + gs * 8 + j) * 128 + o] = acc[j];
}

// ---------------- per-block 9 pixel-types: dconv1 combine + relu + dconv2 ----------------
__global__ void k_xblk(const float* __restrict__ b1d, const float* __restrict__ dw2,
                       const float* __restrict__ db2) {
    __shared__ float sz[9 * 132];
    __shared__ float sw2[3 * 128];
    int g = blockIdx.x;
    int n = g >> 6, bi = (g >> 3) & 7, bj = g & 7;
    int o = threadIdx.x;  // 128
    for (int i = o; i < 384; i += 128) sw2[i] = dw2[i];
    float bo = b1d[o];
#pragma unroll
    for (int ti = 0; ti < 3; ti++)
#pragma unroll
        for (int tj = 0; tj < 3; tj++) {
            float s = bo;
#pragma unroll
            for (int di = 0; di < 3; di++)
#pragma unroll
                for (int dj = 0; dj < 3; dj++) {
                    int roff = (ti == 0 && di == 0) ? -1 : ((ti == 2 && di == 2) ? 1 : 0);
                    int coff = (tj == 0 && dj == 0) ? -1 : ((tj == 2 && dj == 2) ? 1 : 0);
                    int bi2 = bi + roff, bj2 = bj + coff;
                    if (bi2 >= 0 && bi2 < 8 && bj2 >= 0 && bj2 < 8)
                        s += g_q[((di * 3 + dj) * 2048 + (n * 64 + bi2 * 8 + bj2)) * 128 + o];
                }
            sz[(ti * 3 + tj) * 132 + o] = fmaxf(s, 0.f);
        }
    __syncthreads();
    if (o < 27) {
        int ty = o / 3, co = o % 3;
        float acc = db2[co];
#pragma unroll 4
        for (int c = 0; c < 128; c++)
            acc = fmaf(sw2[co * 128 + c], sz[ty * 132 + c], acc);
        g_xblk[(ty * 3 + co) * 2048 + g] = acc;
    }
}

// ---------------- scatter x_hat ----------------
__global__ void k_scatter(float* __restrict__ dout) {
    int id = blockIdx.x * 256 + threadIdx.x;
    if (id >= 32 * 3 * 128 * 128) return;
    int j = id & 127;
    int i = (id >> 7) & 127;
    int co = (id >> 14) % 3;
    int n = id / (3 * 16384);
    int im = i & 15, jm = j & 15;
    int ti = (im == 0) ? 0 : ((im == 15) ? 2 : 1);
    int tj = (jm == 0) ? 0 : ((jm == 15) ? 2 : 1);
    int g = n * 64 + (i >> 4) * 8 + (j >> 4);
    dout[id] = g_xblk[((ti * 3 + tj) * 3 + co) * 2048 + g];
}

// ---------------- finalize: idx (as float) + vq_loss ----------------
__global__ void k_final(float* __restrict__ dout) {
    int id = blockIdx.x * 256 + threadIdx.x;
    if (id < 2048) dout[OFF_IDX + id] = (float)g_idx[id];
    else if (id == 2048) dout[OFF_LOSS] = 1.25f * g_loss * (1.0f / 131072.0f);
}

// ---------------- launcher ----------------
extern "C" void kernel_launch(void* const* d_in, const int* in_sizes, int n_in,
                              void* d_out, int out_size) {
    const float* x   = (const float*)d_in[0];
    const float* w1  = (const float*)d_in[1];
    const float* b1  = (const float*)d_in[2];
    const float* w2  = (const float*)d_in[3];
    const float* b2  = (const float*)d_in[4];
    const float* pw  = (const float*)d_in[5];
    const float* pb  = (const float*)d_in[6];
    const float* cb  = (const float*)d_in[7];
    const float* dpw = (const float*)d_in[8];
    const float* dpb = (const float*)d_in[9];
    const float* w1d = (const float*)d_in[10];
    const float* b1d = (const float*)d_in[11];
    const float* dw2 = (const float*)d_in[12];
    const float* db2 = (const float*)d_in[13];
    float* out = (float*)d_out;

    cudaFuncSetAttribute(k_conv2pool, cudaFuncAttributeMaxDynamicSharedMemorySize, 80 * 1024);
    cudaFuncSetAttribute(k_vq, cudaFuncAttributeMaxDynamicSharedMemorySize, 140 * 1024);

    int wout = (out_size >= OUT_FULL) ? 1 : 0;

    k_prep<<<576, 256>>>(w2, w1d);
    k_conv1<<<dim3(4, 4, 32), 256>>>(x, w1, b1);
    k_conv2pool<<<dim3(8, 2, 32), 256, (16 * 9 * 66 + 16 * 9 * 64) * 4>>>(b2);
    k_proj<<<256, 256>>>(pw, pb, out, wout);
    k_vq<<<256, 256, (512 * 65 + 8 * 64) * 4>>>(cb);
    k_dec_r<<<256, 128>>>(cb, dpw, dpb);
    k_q<<<dim3(128, 9), 256>>>();
    k_xblk<<<2048, 128>>>(b1d, dw2, db2);
    k_scatter<<<6144, 256>>>(out);
    if (wout) k_final<<<9, 256>>>(out);
}

// round 4
// speedup vs baseline: 1.5910x; 1.5910x over previous
#include <cuda_runtime.h>
#include <cstdint>

// ---------------- constants ----------------
#define OFF_IDX   1572864
#define OFF_LOSS  1574912
#define OFF_ZE    1574913
#define OUT_FULL  1705985

// ---------------- scratch (device globals) ----------------
__device__ float g_h1[32 * 64 * 64 * 128];   // conv1 output, CHANNELS-LAST: [n][y][x][c]
__device__ float g_hp[32 * 128 * 64];        // pooled encoder features [n][c][bi*8+bj]
__device__ float g_ze[2048 * 64];            // z_e as [p][d]
__device__ int   g_idx[2048];
__device__ float g_loss;
__device__ float g_r[2048 * 128];            // relu(dproj(z_q)) as [p][c]
__device__ float g_q[9 * 2048 * 128];        // per-tap block contractions [t][g][o]
__device__ float g_xblk[27 * 2048];          // 9 pixel-types x 3 ch per block
__device__ float g_wB2[36 * 8192];           // conv2 weights hi/lo, fragment-native layout
__device__ float g_wt1[9 * 128 * 128];       // dconv1_w transposed: [tap][c][o]

// ---------------- small PTX helpers (generic-target only) ----------------
__device__ __forceinline__ uint32_t smem_u32(const void* p) {
    uint32_t a;
    asm("{ .reg .u64 t; cvta.to.shared.u64 t, %1; cvt.u32.u64 %0, t; }" : "=r"(a) : "l"(p));
    return a;
}
__device__ __forceinline__ void cp16(uint32_t dst, const void* src, uint32_t srcsize) {
    asm volatile("cp.async.cg.shared.global [%0], [%1], 16, %2;"
                 :: "r"(dst), "l"(src), "r"(srcsize) : "memory");
}
#define CP_COMMIT asm volatile("cp.async.commit_group;" ::: "memory")
#define CP_WAIT(n) asm volatile("cp.async.wait_group %0;" :: "n"(n) : "memory")

__device__ __forceinline__ uint32_t to_tf32(float x) {
    uint32_t u;
    asm("cvt.rna.tf32.f32 %0, %1;" : "=r"(u) : "f"(x));
    return u;
}
__device__ __forceinline__ void split_tf32(float x, uint32_t& hi, uint32_t& lo) {
    hi = to_tf32(x);
    lo = to_tf32(x - __uint_as_float(hi));
}
// m16n8k8 tf32 MMA (generic PTX, sm_80+)
__device__ __forceinline__ void mma1688(float* c, const uint32_t* a, const uint32_t* b) {
    asm volatile(
        "mma.sync.aligned.m16n8k8.row.col.f32.tf32.tf32.f32 "
        "{%0,%1,%2,%3}, {%4,%5,%6,%7}, {%8,%9}, {%0,%1,%2,%3};"
        : "+f"(c[0]), "+f"(c[1]), "+f"(c[2]), "+f"(c[3])
        : "r"(a[0]), "r"(a[1]), "r"(a[2]), "r"(a[3]), "r"(b[0]), "r"(b[1]));
}

// ---------------- prep: weight reorders (hi/lo split) + loss zero ----------------
// B fragment-native layout:
//   float index = stage*8192 + wn*4096 + kk*1024 + ni*128 + lane*4 + j
//   oc = wn*64 + ni*8 + (lane>>2); lt = lane&3; k = kk*8 + lt + ((j&1)?4:0)
//   j<2 -> hi(tf32 of w), j>=2 -> lo(tf32 of w - hi); w = w2[(oc*128 + cs*32 + k)*9 + tap]
__global__ void k_prep(const float* __restrict__ w2, const float* __restrict__ w1d) {
    int id = blockIdx.x * 256 + threadIdx.x;
    if (id == 0) g_loss = 0.f;
    if (id < 36 * 8192) {
        int j = id & 3;
        int lane = (id >> 2) & 31;
        int ni = (id >> 7) & 7;
        int kk = (id >> 10) & 3;
        int wn = (id >> 12) & 1;
        int stage = id >> 13;
        int lg = lane >> 2, lt = lane & 3;
        int oc = wn * 64 + ni * 8 + lg;
        int k = kk * 8 + lt + ((j & 1) ? 4 : 0);
        int tap = stage >> 2, cs = stage & 3;
        float w = w2[(oc * 128 + cs * 32 + k) * 9 + tap];
        uint32_t hi, lo;
        split_tf32(w, hi, lo);
        g_wB2[id] = __uint_as_float((j < 2) ? hi : lo);
    }
    if (id < 9 * 128 * 128) {
        int t = id / 16384, rem = id % 16384, c = rem / 128, o = rem % 128;
        g_wt1[id] = w1d[(o * 128 + c) * 9 + t];
    }
}

// ---------------- conv1: 3->128, 3x3, stride2, pad1, relu; channels-last out ----------------
__global__ void k_conv1(const float* __restrict__ x, const float* __restrict__ w,
                        const float* __restrict__ b) {
    __shared__ float sw[128 * 27];
    __shared__ float sb[128];
    int n = blockIdx.z, yt = blockIdx.y, xt = blockIdx.x;
    int tid = threadIdx.x;
    for (int i = tid; i < 128 * 27; i += 256) sw[i] = w[i];
    if (tid < 128) sb[tid] = b[tid];
    int ox = xt * 16 + (tid & 15);
    int oy = yt * 16 + (tid >> 4);
    float iv[27];
    const float* xb = x + n * 3 * 16384;
#pragma unroll
    for (int c = 0; c < 3; c++)
#pragma unroll
        for (int di = 0; di < 3; di++) {
            int gy = 2 * oy + di - 1;
#pragma unroll
            for (int dj = 0; dj < 3; dj++) {
                int gx = 2 * ox + dj - 1;
                float v = 0.f;
                if (gy >= 0 && gy < 128 && gx >= 0 && gx < 128)
                    v = xb[(c * 128 + gy) * 128 + gx];
                iv[c * 9 + di * 3 + dj] = v;
            }
        }
    __syncthreads();
    float* ob = g_h1 + ((n * 64 + oy) * 64 + ox) * 128;
#pragma unroll 2
    for (int o4 = 0; o4 < 128; o4 += 4) {
        float4 r;
        float a0 = sb[o4], a1 = sb[o4 + 1], a2 = sb[o4 + 2], a3 = sb[o4 + 3];
#pragma unroll
        for (int k = 0; k < 27; k++) {
            float v = iv[k];
            a0 = fmaf(sw[(o4 + 0) * 27 + k], v, a0);
            a1 = fmaf(sw[(o4 + 1) * 27 + k], v, a1);
            a2 = fmaf(sw[(o4 + 2) * 27 + k], v, a2);
            a3 = fmaf(sw[(o4 + 3) * 27 + k], v, a3);
        }
        r.x = fmaxf(a0, 0.f); r.y = fmaxf(a1, 0.f);
        r.z = fmaxf(a2, 0.f); r.w = fmaxf(a3, 0.f);
        *(float4*)(ob + o4) = r;
    }
}

// ---------------- conv2 via mma.sync tf32x3 + fused 4x4 avgpool ----------------
// grid 256 = n*8 + t; 256 threads / 8 warps (4 wm x 2 wn); warp tile 32(M) x 64(N).
// M=128 = 4 conv rows x 32 cols; K=1152 in 36 stages of 32; cp.async double-buffered.
// A raw fp32 in smem (split to hi/lo in regs); B pre-split hi/lo, fragment-native.
#define C2_AT 18432                          // A tile bytes (128 rows * 144B)
#define C2_BT 32768                          // B tile bytes (8192 floats)
#define C2_SMEM (2 * C2_AT + 2 * C2_BT)      // 102400 B

__device__ __forceinline__ void c2_load_stage(uint32_t smb, int buf, int s,
                                              int n, int t, int tid) {
    int tap = s >> 2, cs = s & 3;
    int di = tap / 3, dj = tap % 3;
    uint32_t abase = smb + buf * C2_AT;
    uint32_t bbase = smb + 2 * C2_AT + buf * C2_BT;
#pragma unroll
    for (int j = 0; j < 4; j++) {
        int c = j * 256 + tid;
        int m = c >> 3, u = c & 7;
        int oy = t * 4 + (m >> 5), ox = m & 31;
        int gy = 2 * oy + di - 1, gx = 2 * ox + dj - 1;
        bool ok = (gy >= 0 && gy < 64 && gx >= 0 && gx < 64);
        const float* src = ok ? (g_h1 + ((n * 64 + gy) * 64 + gx) * 128 + cs * 32 + u * 4)
                              : g_h1;
        cp16(abase + m * 144 + u * 16, src, ok ? 16u : 0u);
    }
#pragma unroll
    for (int j = 0; j < 8; j++) {
        int idx = j * 256 + tid;
        cp16(bbase + idx * 16, g_wB2 + s * 8192 + idx * 4, 16u);
    }
    CP_COMMIT;
}

__global__ __launch_bounds__(256, 2) void k_conv2m(const float* __restrict__ b2) {
    extern __shared__ char sm[];
    uint32_t smb = smem_u32(sm);
    int tid = threadIdx.x;
    int warp = tid >> 5, lane = tid & 31;
    int wm = warp >> 1, wn = warp & 1;
    int lg = lane >> 2, lt = lane & 3;
    int bid = blockIdx.x;
    int n = bid >> 3, t = bid & 7;

    float acc[2][8][4];
#pragma unroll
    for (int mi = 0; mi < 2; mi++)
#pragma unroll
        for (int ni = 0; ni < 8; ni++)
#pragma unroll
            for (int r = 0; r < 4; r++) acc[mi][ni][r] = 0.f;

    c2_load_stage(smb, 0, 0, n, t, tid);

    for (int s = 0; s < 36; s++) {
        int buf = s & 1;
        if (s + 1 < 36) c2_load_stage(smb, buf ^ 1, s + 1, n, t, tid);
        if (s + 1 < 36) { CP_WAIT(1); } else { CP_WAIT(0); }
        __syncthreads();
        const uint32_t* As = (const uint32_t*)(sm + buf * C2_AT);
        const char* Bs = sm + 2 * C2_AT + buf * C2_BT;
#pragma unroll
        for (int kk = 0; kk < 4; kk++) {
            int k0 = kk * 8;
            uint32_t ahi[2][4], alo[2][4];
#pragma unroll
            for (int mi = 0; mi < 2; mi++) {
                int r = wm * 32 + mi * 16 + lg;
                uint32_t raw0 = As[r * 36 + k0 + lt];
                uint32_t raw1 = As[(r + 8) * 36 + k0 + lt];
                uint32_t raw2 = As[r * 36 + k0 + lt + 4];
                uint32_t raw3 = As[(r + 8) * 36 + k0 + lt + 4];
                split_tf32(__uint_as_float(raw0), ahi[mi][0], alo[mi][0]);
                split_tf32(__uint_as_float(raw1), ahi[mi][1], alo[mi][1]);
                split_tf32(__uint_as_float(raw2), ahi[mi][2], alo[mi][2]);
                split_tf32(__uint_as_float(raw3), ahi[mi][3], alo[mi][3]);
            }
#pragma unroll
            for (int ni = 0; ni < 8; ni++) {
                float4 bv = *(const float4*)(Bs + (((wn * 4 + kk) * 8 + ni) * 32 + lane) * 16);
                uint32_t bhi[2] = {__float_as_uint(bv.x), __float_as_uint(bv.y)};
                uint32_t blo[2] = {__float_as_uint(bv.z), __float_as_uint(bv.w)};
#pragma unroll
                for (int mi = 0; mi < 2; mi++) {
                    mma1688(acc[mi][ni], ahi[mi], bhi);
                    mma1688(acc[mi][ni], alo[mi], bhi);
                    mma1688(acc[mi][ni], ahi[mi], blo);
                }
            }
        }
        __syncthreads();
    }

    // ---- epilogue: accum -> smem, bias+relu+4x4 pool -> g_hp ----
    float* eb = (float*)sm;  // [m 0..127][oc 0..127] stride 132
#pragma unroll
    for (int mi = 0; mi < 2; mi++)
#pragma unroll
        for (int ni = 0; ni < 8; ni++) {
            int m = wm * 32 + mi * 16 + lg;
            int oc = wn * 64 + ni * 8 + 2 * lt;
            eb[m * 132 + oc]           = acc[mi][ni][0];
            eb[m * 132 + oc + 1]       = acc[mi][ni][1];
            eb[(m + 8) * 132 + oc]     = acc[mi][ni][2];
            eb[(m + 8) * 132 + oc + 1] = acc[mi][ni][3];
        }
    __syncthreads();
    for (int i = tid; i < 1024; i += 256) {
        int pc = i >> 7, oc = i & 127;
        float bv = __ldg(&b2[oc]);
        float s = 0.f;
#pragma unroll
        for (int oyl = 0; oyl < 4; oyl++)
#pragma unroll
            for (int dx = 0; dx < 4; dx++) {
                int m = oyl * 32 + pc * 4 + dx;
                s += fmaxf(eb[m * 132 + oc] + bv, 0.f);
            }
        g_hp[(n * 128 + oc) * 64 + t * 8 + pc] = s * (1.f / 16.f);
    }
}

// ---------------- proj 1x1: 128 -> 64 (z_e) ----------------
__global__ void k_proj(const float* __restrict__ pw, const float* __restrict__ pb,
                       float* __restrict__ dout, int write_out) {
    __shared__ float spw[64 * 129];
    __shared__ float shp[8][128];
    int blk = blockIdx.x;
    int tid = threadIdx.x;
    for (int i = tid; i < 64 * 128; i += 256) {
        int d = i >> 7, c = i & 127;
        spw[d * 129 + c] = pw[i];
    }
    for (int i = tid; i < 8 * 128; i += 256) {
        int pl = i >> 7, c = i & 127;
        int p = blk * 8 + pl;
        shp[pl][c] = g_hp[((p >> 6) * 128 + c) * 64 + (p & 63)];
    }
    __syncthreads();
    int d = tid & 63;
    int pl0 = tid >> 6;
    for (int pl = pl0; pl < 8; pl += 4) {
        int p = blk * 8 + pl;
        float acc = pb[d];
#pragma unroll 4
        for (int c = 0; c < 128; c++) acc = fmaf(spw[d * 129 + c], shp[pl][c], acc);
        g_ze[p * 64 + d] = acc;
        if (write_out) {
            int nn = p >> 6, pos = p & 63;
            dout[OFF_ZE + (nn * 64 + d) * 64 + pos] = acc;
        }
    }
}

// ---------------- vector quantizer ----------------
__global__ void k_vq(const float* __restrict__ cb) {
    extern __shared__ float smv[];
    float* scb = smv;
    float* sze = smv + 512 * 65;
    int tid = threadIdx.x;
    for (int i = tid; i < 512 * 64; i += 256) {
        int c = i >> 6, d = i & 63;
        scb[c * 65 + d] = cb[i];
    }
    for (int i = tid; i < 8 * 64; i += 256)
        sze[i] = g_ze[blockIdx.x * 8 * 64 + i];
    __syncthreads();
    int warp = tid >> 5, lane = tid & 31;
    int p = blockIdx.x * 8 + warp;
    const float* zp = sze + warp * 64;
    float best = 3.4e38f; int bidx = 0;
    for (int ci = 0; ci < 16; ci++) {
        int c = ci * 32 + lane;
        const float* cr = scb + c * 65;
        float dd = 0.f;
#pragma unroll 8
        for (int d = 0; d < 64; d++) {
            float tdf = zp[d] - cr[d];
            dd = fmaf(tdf, tdf, dd);
        }
        if (dd < best) { best = dd; bidx = c; }
    }
#pragma unroll
    for (int off = 16; off > 0; off >>= 1) {
        float ob = __shfl_down_sync(0xffffffffu, best, off);
        int   oi = __shfl_down_sync(0xffffffffu, bidx, off);
        if (ob < best || (ob == best && oi < bidx)) { best = ob; bidx = oi; }
    }
    if (lane == 0) {
        g_idx[p] = bidx;
        atomicAdd(&g_loss, best);
    }
}

// ---------------- decoder 1x1 dproj + relu ----------------
__global__ void k_dec_r(const float* __restrict__ cb, const float* __restrict__ dpw,
                        const float* __restrict__ dpb) {
    __shared__ float sdw[128 * 65];
    __shared__ float scr[8][64];
    int tid = threadIdx.x;
    for (int i = tid; i < 128 * 64; i += 128) {
        int c = i >> 6, d = i & 63;
        sdw[c * 65 + d] = dpw[i];
    }
    for (int i = tid; i < 8 * 64; i += 128) {
        int pl = i >> 6, d = i & 63;
        int p = blockIdx.x * 8 + pl;
        scr[pl][d] = cb[g_idx[p] * 64 + d];
    }
    __syncthreads();
    int c = tid;
    float bv = dpb[c];
    for (int pl = 0; pl < 8; pl++) {
        float acc = bv;
#pragma unroll 4
        for (int d = 0; d < 64; d++) acc = fmaf(sdw[c * 65 + d], scr[pl][d], acc);
        g_r[(blockIdx.x * 8 + pl) * 128 + c] = fmaxf(acc, 0.f);
    }
}

// ---------------- per-tap block contractions ----------------
__global__ void k_q() {
    __shared__ float sr[16 * 128];
    int t = blockIdx.y;
    int gt = blockIdx.x;
    int tid = threadIdx.x;
    for (int i = tid; i < 16 * 128; i += 256)
        sr[i] = g_r[gt * 16 * 128 + i];
    __syncthreads();
    int o = tid & 127, gs = tid >> 7;
    float acc[8];
#pragma unroll
    for (int j = 0; j < 8; j++) acc[j] = 0.f;
    const float* wp = g_wt1 + t * 16384 + o;
    const float* rp = sr + gs * 8 * 128;
#pragma unroll 4
    for (int c = 0; c < 128; c++) {
        float wv = wp[c * 128];
#pragma unroll
        for (int j = 0; j < 8; j++) acc[j] = fmaf(wv, rp[j * 128 + c], acc[j]);
    }
#pragma unroll
    for (int j = 0; j < 8; j++)
        g_q[(t * 2048 + gt * 16 + gs * 8 + j) * 128 + o] = acc[j];
}

// ---------------- per-block pixel types ----------------
__global__ void k_xblk(const float* __restrict__ b1d, const float* __restrict__ dw2,
                       const float* __restrict__ db2) {
    __shared__ float sz[9 * 132];
    __shared__ float sw2[3 * 128];
    int g = blockIdx.x;
    int n = g >> 6, bi = (g >> 3) & 7, bj = g & 7;
    int o = threadIdx.x;
    for (int i = o; i < 384; i += 128) sw2[i] = dw2[i];
    float bo = b1d[o];
#pragma unroll
    for (int ti = 0; ti < 3; ti++)
#pragma unroll
        for (int tj = 0; tj < 3; tj++) {
            float s = bo;
#pragma unroll
            for (int di = 0; di < 3; di++)
#pragma unroll
                for (int dj = 0; dj < 3; dj++) {
                    int roff = (ti == 0 && di == 0) ? -1 : ((ti == 2 && di == 2) ? 1 : 0);
                    int coff = (tj == 0 && dj == 0) ? -1 : ((tj == 2 && dj == 2) ? 1 : 0);
                    int bi2 = bi + roff, bj2 = bj + coff;
                    if (bi2 >= 0 && bi2 < 8 && bj2 >= 0 && bj2 < 8)
                        s += g_q[((di * 3 + dj) * 2048 + (n * 64 + bi2 * 8 + bj2)) * 128 + o];
                }
            sz[(ti * 3 + tj) * 132 + o] = fmaxf(s, 0.f);
        }
    __syncthreads();
    if (o < 27) {
        int ty = o / 3, co = o % 3;
        float acc = db2[co];
#pragma unroll 4
        for (int c = 0; c < 128; c++)
            acc = fmaf(sw2[co * 128 + c], sz[ty * 132 + c], acc);
        g_xblk[(ty * 3 + co) * 2048 + g] = acc;
    }
}

// ---------------- scatter x_hat ----------------
__global__ void k_scatter(float* __restrict__ dout) {
    int id = blockIdx.x * 256 + threadIdx.x;
    if (id >= 32 * 3 * 128 * 128) return;
    int j = id & 127;
    int i = (id >> 7) & 127;
    int co = (id >> 14) % 3;
    int n = id / (3 * 16384);
    int im = i & 15, jm = j & 15;
    int ti = (im == 0) ? 0 : ((im == 15) ? 2 : 1);
    int tj = (jm == 0) ? 0 : ((jm == 15) ? 2 : 1);
    int g = n * 64 + (i >> 4) * 8 + (j >> 4);
    dout[id] = g_xblk[((ti * 3 + tj) * 3 + co) * 2048 + g];
}

// ---------------- finalize ----------------
__global__ void k_final(float* __restrict__ dout) {
    int id = blockIdx.x * 256 + threadIdx.x;
    if (id < 2048) dout[OFF_IDX + id] = (float)g_idx[id];
    else if (id == 2048) dout[OFF_LOSS] = 1.25f * g_loss * (1.0f / 131072.0f);
}

// ---------------- launcher ----------------
extern "C" void kernel_launch(void* const* d_in, const int* in_sizes, int n_in,
                              void* d_out, int out_size) {
    const float* x   = (const float*)d_in[0];
    const float* w1  = (const float*)d_in[1];
    const float* b1  = (const float*)d_in[2];
    const float* w2  = (const float*)d_in[3];
    const float* b2  = (const float*)d_in[4];
    const float* pw  = (const float*)d_in[5];
    const float* pb  = (const float*)d_in[6];
    const float* cb  = (const float*)d_in[7];
    const float* dpw = (const float*)d_in[8];
    const float* dpb = (const float*)d_in[9];
    const float* w1d = (const float*)d_in[10];
    const float* b1d = (const float*)d_in[11];
    const float* dw2 = (const float*)d_in[12];
    const float* db2 = (const float*)d_in[13];
    float* out = (float*)d_out;

    cudaFuncSetAttribute(k_conv2m, cudaFuncAttributeMaxDynamicSharedMemorySize, C2_SMEM);
    cudaFuncSetAttribute(k_vq, cudaFuncAttributeMaxDynamicSharedMemorySize, 140 * 1024);

    int wout = (out_size >= OUT_FULL) ? 1 : 0;

    k_prep<<<1152, 256>>>(w2, w1d);
    k_conv1<<<dim3(4, 4, 32), 256>>>(x, w1, b1);
    k_conv2m<<<256, 256, C2_SMEM>>>(b2);
    k_proj<<<256, 256>>>(pw, pb, out, wout);
    k_vq<<<256, 256, (512 * 65 + 8 * 64) * 4>>>(cb);
    k_dec_r<<<256, 128>>>(cb, dpw, dpb);
    k_q<<<dim3(128, 9), 256>>>();
    k_xblk<<<2048, 128>>>(b1d, dw2, db2);
    k_scatter<<<6144, 256>>>(out);
    if (wout) k_final<<<9, 256>>>(out);
}